// round 6
// baseline (speedup 1.0000x reference)
#include <cuda_runtime.h>
#include <cuda_bf16.h>

// Fixed shapes
#define H_DIM   1024
#define N_DIM   64
#define SEQ_L   2048
#define LHALF   1024               // l-range per block
#define CHUNK   32                 // l-values per (c, q) thread
#define NCH     (LHALF / CHUNK)    // 32 chunks per block
#define KHALF   (CHUNK / 2)        // 16 packed k-steps

typedef unsigned long long ull;
__device__ __forceinline__ ull pack2(float lo, float hi) {
    ull r; asm("mov.b64 %0, {%1, %2};" : "=l"(r) : "f"(lo), "f"(hi)); return r;
}
__device__ __forceinline__ void unpack2(ull v, float& lo, float& hi) {
    asm("mov.b64 {%0, %1}, %2;" : "=f"(lo), "=f"(hi) : "l"(v));
}
__device__ __forceinline__ ull fma2(ull a, ull b, ull c) {
    ull d; asm("fma.rn.f32x2 %0, %1, %2, %3;" : "=l"(d) : "l"(a), "l"(b), "l"(c)); return d;
}
__device__ __forceinline__ ull mul2(ull a, ull b) {
    ull d; asm("mul.rn.f32x2 %0, %1, %2;" : "=l"(d) : "l"(a), "l"(b)); return d;
}

// ============================================================================
// One block per (h, l-half), 128 threads.
// Phase 1: threads (n, sub): params per n; chunk seeds (y0,y1) via packed
//          stride-32 order-2 recurrence.
// Phase 2: threads (c, q): packed stride-2 recurrence on the fma pipe,
//          accumulation as SCALAR FADDs (alu pipe) on unpacked halves.
// Phase 3: balanced single-round reduction, scalar adds.
// ============================================================================
__global__ void __launch_bounds__(128) ssk_fused(
    const float* __restrict__ Cri, const float* __restrict__ logdt,
    const float* __restrict__ Bri, const float* __restrict__ invAr,
    const float* __restrict__ Aim, float* __restrict__ out)
{
    __shared__ float2 s_seed[N_DIM * NCH];   // 16KB, [n][c ^ (n&31)]
    __shared__ float4 s_par4[N_DIM];         // 1KB, (p2, p2, q2, q2) duplicated
    __shared__ float2 s_par1[N_DIM];         // 0.5KB, (p1, q1)

    const int tx   = threadIdx.x;            // 0..127
    const int h    = blockIdx.x >> 1;
    const int half = blockIdx.x & 1;

    // ---------------- Phase 1: params + packed seed march ----------------
    {
        const int n   = tx & 63;
        const int sub = tx >> 6;
        const int idx = h * N_DIM + n;
        const int nm  = n & 31;

        float cr = Cri[2 * idx], ci = Cri[2 * idx + 1];
        float br = Bri[2 * idx], bi = Bri[2 * idx + 1];
        float dt = __expf(logdt[h]);
        float Ar = -__expf(invAr[idx]);
        float Ai = Aim[idx];

        float zr = Ar * dt, zi = Ai * dt;
        float dr = 1.0f - 0.5f * zr, di = -0.5f * zi;
        float inv = 1.0f / (dr * dr + di * di);

        float bcr = br * cr - bi * ci;
        float bci = br * ci + bi * cr;
        float s = 2.0f * dt * inv;
        float ctr = (bcr * dr + bci * di) * s;   // Ct2 = 2*B*C*dt/den
        float cti = (bci * dr - bcr * di) * s;

        float nr = 1.0f + 0.5f * zr, ni = 0.5f * zi;
        float rr = (nr * dr + ni * di) * inv;    // r, |r| < 1
        float ri = (ni * dr - nr * di) * inv;

        float m2  = rr * rr + ri * ri;           // |r|^2
        float r2r = rr * rr - ri * ri;
        float r2i = 2.0f * rr * ri;
        if (sub == 0) {
            s_par4[n] = make_float4(2.0f * r2r, 2.0f * r2r,
                                    -(m2 * m2), -(m2 * m2));
            s_par1[n] = make_float2(2.0f * rr, -m2);
        }

        // s32 = r^32 : 4 squarings of r^2
        float sr = r2r, si = r2i;
#pragma unroll
        for (int i = 0; i < 4; i++) {
            float tr = sr * sr - si * si;
            si = 2.0f * sr * si;
            sr = tr;
        }
        const float p32 = 2.0f * sr;
        const float q32 = -(sr * sr + si * si);  // -|r^32|^2

        // w = Ct2 * r^(512*t), t = 2*half + sub
        float wr = ctr, wi = cti;
        const int t = 2 * half + sub;
        if (t) {
            float pr = sr, pi = si;              // -> r^512
#pragma unroll
            for (int i = 0; i < 4; i++) {
                float tr = pr * pr - pi * pi;
                pi = 2.0f * pr * pi;
                pr = tr;
            }
            float mr = pr, mi = pi;              // r^512
            if (t & 2) {
                float qr = pr * pr - pi * pi;    // r^1024
                float qi = 2.0f * pr * pi;
                if (t & 1) {                     // r^1536
                    float tr = qr * pr - qi * pi;
                    qi = qr * pi + qi * pr;
                    qr = tr;
                }
                mr = qr; mi = qi;
            }
            float tr = wr * mr - wi * mi;
            wi = wr * mi + wi * mr;
            wr = tr;
        }

        // First two chunk seeds
        float w1r  = wr * rr - wi * ri;
        float w1i  = wr * ri + wi * rr;
        float w32r = wr * sr - wi * si;
        float w33r = w1r * sr - w1i * si;

        const int cb = sub * 16;
        ull* sp = (ull*)s_seed + n * NCH;
        ull vP = pack2(wr, w1r);
        ull vC = pack2(w32r, w33r);
        sp[cb ^ nm]       = vP;
        sp[(cb + 1) ^ nm] = vC;

        const ull p32v = pack2(p32, p32);
        const ull q32v = pack2(q32, q32);
#pragma unroll
        for (int i = 2; i < 16; i++) {
            ull vN = fma2(p32v, vC, mul2(q32v, vP));
            sp[(cb + i) ^ nm] = vN;
            vP = vC; vC = vN;
        }
    }
    __syncthreads();

    // ---------------- Phase 2: packed recurrence, scalar accumulate ------
    const int c = tx & 31;                       // chunk (lane)
    const int q = tx >> 5;                       // quarter (warp)

    float accE[KHALF], accO[KHALF];              // even/odd l within pair
#pragma unroll
    for (int k = 0; k < KHALF; k++) { accE[k] = 0.0f; accO[k] = 0.0f; }

    const int n0 = q * 16;
#pragma unroll 1
    for (int np = 0; np < 8; np++) {
        const int na = n0 + 2 * np;
        const int nb = na + 1;

        ulonglong2 pqa = *((const ulonglong2*)&s_par4[na]);  // (p2,p2),(q2,q2)
        ulonglong2 pqb = *((const ulonglong2*)&s_par4[nb]);
        float2 ra = s_par1[na];                              // (p1, q1)
        float2 rb = s_par1[nb];
        float2 sa = s_seed[na * NCH + (c ^ (na & 31))];
        float2 sb = s_seed[nb * NCH + (c ^ (nb & 31))];

        // reconstruct y2, y3 via stride-1 recurrence
        float y2a = fmaf(ra.x, sa.y, ra.y * sa.x);
        float y3a = fmaf(ra.x, y2a, ra.y * sa.y);
        float y2b = fmaf(rb.x, sb.y, rb.y * sb.x);
        float y3b = fmaf(rb.x, y2b, rb.y * sb.y);

        ull vpA = pack2(sa.x, sa.y), vcA = pack2(y2a, y3a);
        ull vpB = pack2(sb.x, sb.y), vcB = pack2(y2b, y3b);

        accE[0] += sa.x + sb.x;
        accO[0] += sa.y + sb.y;
        accE[1] += y2a + y2b;
        accO[1] += y3a + y3b;

#pragma unroll
        for (int k = 2; k < KHALF; k++) {
            ull nA = fma2(pqa.x, vcA, mul2(pqa.y, vpA));     // fma pipe
            ull nB = fma2(pqb.x, vcB, mul2(pqb.y, vpB));     // fma pipe
            float a0, a1, b0, b1;
            unpack2(nA, a0, a1);                             // reg renames
            unpack2(nB, b0, b1);
            accE[k] += a0 + b0;                              // scalar adds
            accO[k] += a1 + b1;
            vpA = vcA; vcA = nA;
            vpB = vcB; vcB = nB;
        }
    }

    // ------------- Phase 3: balanced single-round reduction -------------
    __syncthreads();                              // seeds no longer needed
    float2* red = (float2*)s_seed;                // 16KB = 16k x 4q x 32c

#pragma unroll
    for (int k = 0; k < KHALF; k++)
        red[k * 128 + q * 32 + c] = make_float2(accE[k], accO[k]);
    __syncthreads();

    // warp q reduces k in [4q, 4q+4) over quarters, stores 8 floats
    {
        const int kb = 4 * q;
        float2 sum[4];
#pragma unroll
        for (int j = 0; j < 4; j++) {
            const int row = (kb + j) * 128 + c;
            float2 v0 = red[row],      v1 = red[row + 32];
            float2 v2 = red[row + 64], v3 = red[row + 96];
            sum[j] = make_float2((v0.x + v1.x) + (v2.x + v3.x),
                                 (v0.y + v1.y) + (v2.y + v3.y));
        }
        float4* op = (float4*)(out + (size_t)h * SEQ_L
                               + half * LHALF + c * CHUNK + 8 * q);
        op[0] = make_float4(sum[0].x, sum[0].y, sum[1].x, sum[1].y);
        op[1] = make_float4(sum[2].x, sum[2].y, sum[3].x, sum[3].y);
    }
}

extern "C" void kernel_launch(void* const* d_in, const int* in_sizes, int n_in,
                              void* d_out, int out_size)
{
    const float* Cri   = (const float*)d_in[0];   // (1, H, N, 2)
    const float* logdt = (const float*)d_in[1];   // (H,)
    const float* Bri   = (const float*)d_in[2];   // (H, N, 2) (n_ssm == H)
    const float* invAr = (const float*)d_in[3];   // (H, N)
    const float* Aim   = (const float*)d_in[4];   // (H, N)
    float* out = (float*)d_out;                   // (1, H, L)

    ssk_fused<<<H_DIM * 2, 128>>>(Cri, logdt, Bri, invAr, Aim, out);
}

// round 9
// speedup vs baseline: 1.3582x; 1.3582x over previous
#include <cuda_runtime.h>
#include <cuda_bf16.h>
#include <cstdint>

// Fixed shapes
#define H_DIM   1024
#define N_DIM   64
#define SEQ_L   2048
// Per-h GEMM: D[c=0..127, j=0..15] = sum_k A[c,k]*B[k,j],  l = 16c + j
//   A[c, 2n] = Re(Ct2 * r^(16c)),  A[c, 2n+1] = Im(...)
//   B[2n, j] = Re(r^j),            B[2n+1, j] = -Im(r^j)
// bf16 split A = Ahi+Amid, B = Bhi+Bmid; D = AhBh + AhBm + AmBh.

// SMEM: row-major, 256B rows, XOR-swizzled in 32B units by (row & 7)
#define A_HI_OFF   0        // 128 rows x 256B = 32768
#define A_MID_OFF  32768
#define B_HI_OFF   65536    // 16 rows x 256B = 4096  (stored as [j][kappa])
#define B_MID_OFF  69632
#define SMEM_BYTES 73728

__device__ __forceinline__ uint32_t cvt_bf16x2(float hi_f, float lo_f) {
    // result: upper16 = bf16(hi_f), lower16 = bf16(lo_f)
    uint32_t r;
    asm("cvt.rn.bf16x2.f32 %0, %1, %2;" : "=r"(r) : "f"(hi_f), "f"(lo_f));
    return r;
}

// Split (lo, hi) f32 pair into hi-bf16x2 and mid-bf16x2 (residual), store both.
__device__ __forceinline__ void split_store(char* sm, uint32_t addr,
                                            uint32_t off_hi, uint32_t off_mid,
                                            float lo, float hi) {
    uint32_t pk = cvt_bf16x2(hi, lo);
    float lo_h = __uint_as_float(pk << 16);
    float hi_h = __uint_as_float(pk & 0xFFFF0000u);
    uint32_t pm = cvt_bf16x2(hi - hi_h, lo - lo_h);
    *reinterpret_cast<uint32_t*>(sm + off_hi + addr) = pk;
    *reinterpret_cast<uint32_t*>(sm + off_mid + addr) = pm;
}

__device__ __forceinline__ void mma_bf16(float* d, const uint32_t* a, const uint32_t* b) {
    asm volatile(
        "mma.sync.aligned.m16n8k16.row.col.f32.bf16.bf16.f32 "
        "{%0,%1,%2,%3}, {%4,%5,%6,%7}, {%8,%9}, {%0,%1,%2,%3};"
        : "+f"(d[0]), "+f"(d[1]), "+f"(d[2]), "+f"(d[3])
        : "r"(a[0]), "r"(a[1]), "r"(a[2]), "r"(a[3]), "r"(b[0]), "r"(b[1]));
}

__global__ void __launch_bounds__(128) ssk_hmma(
    const float* __restrict__ Cri, const float* __restrict__ logdt,
    const float* __restrict__ Bri, const float* __restrict__ invAr,
    const float* __restrict__ Aim, float* __restrict__ out)
{
    extern __shared__ __align__(1024) char sm[];
    const int tx = threadIdx.x;
    const int h  = blockIdx.x;

    // ================= Generation phase =================
    {
        const int n    = tx & 63;
        const int half = tx >> 6;
        const int idx  = h * N_DIM + n;

        float cr = Cri[2 * idx], ci = Cri[2 * idx + 1];
        float br = Bri[2 * idx], bi = Bri[2 * idx + 1];
        float dt = __expf(logdt[h]);
        float Ar = -__expf(invAr[idx]);
        float Ai = Aim[idx];

        float zr = Ar * dt, zi = Ai * dt;
        float dr = 1.0f - 0.5f * zr, di = -0.5f * zi;
        float inv = 1.0f / (dr * dr + di * di);

        float bcr = br * cr - bi * ci;
        float bci = br * ci + bi * cr;
        float s = 2.0f * dt * inv;
        float ctr = (bcr * dr + bci * di) * s;      // Ct2 = 2*B*C*dt/den
        float cti = (bci * dr - bcr * di) * s;

        float nr = 1.0f + 0.5f * zr, ni = 0.5f * zi;
        float rr = (nr * dr + ni * di) * inv;       // r, |r| < 1
        float ri = (ni * dr - nr * di) * inv;

        // powers r^2, r^4, r^8, r^16 (= rho)
        float r2r = rr * rr - ri * ri,   r2i = 2.0f * rr * ri;
        float r4r = r2r * r2r - r2i * r2i, r4i = 2.0f * r2r * r2i;
        float r8r = r4r * r4r - r4i * r4i, r8i = 2.0f * r4r * r4i;
        float pr  = r8r * r8r - r8i * r8i, pi  = 2.0f * r8r * r8i;   // rho

        // ---- B tile: rows j = 8*half .. +7; store (Re r^j, -Im r^j) ----
        {
            float vr = 1.0f, vi = 0.0f;
            if (half) { vr = r8r; vi = r8i; }
#pragma unroll
            for (int i = 0; i < 8; i++) {
                int j = 8 * half + i;
                uint32_t addr = (uint32_t)j * 256u
                              + (((uint32_t)n * 4u) ^ (((uint32_t)(j & 7)) << 5));
                split_store(sm, addr, B_HI_OFF, B_MID_OFF, vr, -vi);
                float t = vr * rr - vi * ri;        // v *= r
                vi = vr * ri + vi * rr;
                vr = t;
            }
        }

        // ---- A tile: rows c = 64*half .. +63; W = Ct2 * rho^c ----
        float wr = ctr, wi = cti;
        if (half) {                                  // w *= rho^64 (6 squarings)
            float qr = pr, qi = pi;
#pragma unroll
            for (int i = 0; i < 6; i++) {
                float t = qr * qr - qi * qi;
                qi = 2.0f * qr * qi;
                qr = t;
            }
            float t = wr * qr - wi * qi;
            wi = wr * qi + wi * qr;
            wr = t;
        }
#pragma unroll 4
        for (int i = 0; i < 64; i++) {
            int c = 64 * half + i;
            uint32_t addr = (uint32_t)c * 256u
                          + (((uint32_t)n * 4u) ^ (((uint32_t)(c & 7)) << 5));
            split_store(sm, addr, A_HI_OFF, A_MID_OFF, wr, wi);
            float t = wr * pr - wi * pi;             // w *= rho
            wi = wr * pi + wi * pr;
            wr = t;
        }
    }
    __syncthreads();

    // ================= MMA phase =================
    const int wid = tx >> 5;
    const int lid = tx & 31;
    const int g   = lid >> 2;                       // group id (0..7)
    const int t   = lid & 3;                        // thread in group

    float d[2][2][4];
#pragma unroll
    for (int mt = 0; mt < 2; mt++)
#pragma unroll
        for (int nt = 0; nt < 2; nt++)
#pragma unroll
            for (int i = 0; i < 4; i++) d[mt][nt][i] = 0.0f;

    const int R0 = wid * 32;                        // warp's M base (2 m16 tiles)
    const uint32_t gsw = ((uint32_t)g) << 5;

#pragma unroll
    for (int kt = 0; kt < 8; kt++) {
        const uint32_t k0 = ((uint32_t)(kt * 32 + 4 * t)) ^ gsw;   // bf16 pair k..k+1
        const uint32_t k1 = k0 + 16;                               // k+8..k+9

        uint32_t a_hi[2][4], a_md[2][4], b_hi[2][2], b_md[2][2];
#pragma unroll
        for (int mt = 0; mt < 2; mt++) {
            const uint32_t r0 = (uint32_t)(R0 + mt * 16 + g) * 256u;
            const uint32_t r8 = r0 + 8u * 256u;
            a_hi[mt][0] = *reinterpret_cast<uint32_t*>(sm + A_HI_OFF  + r0 + k0);
            a_hi[mt][1] = *reinterpret_cast<uint32_t*>(sm + A_HI_OFF  + r8 + k0);
            a_hi[mt][2] = *reinterpret_cast<uint32_t*>(sm + A_HI_OFF  + r0 + k1);
            a_hi[mt][3] = *reinterpret_cast<uint32_t*>(sm + A_HI_OFF  + r8 + k1);
            a_md[mt][0] = *reinterpret_cast<uint32_t*>(sm + A_MID_OFF + r0 + k0);
            a_md[mt][1] = *reinterpret_cast<uint32_t*>(sm + A_MID_OFF + r8 + k0);
            a_md[mt][2] = *reinterpret_cast<uint32_t*>(sm + A_MID_OFF + r0 + k1);
            a_md[mt][3] = *reinterpret_cast<uint32_t*>(sm + A_MID_OFF + r8 + k1);
        }
#pragma unroll
        for (int nt = 0; nt < 2; nt++) {
            const uint32_t rb = (uint32_t)(nt * 8 + g) * 256u;
            b_hi[nt][0] = *reinterpret_cast<uint32_t*>(sm + B_HI_OFF  + rb + k0);
            b_hi[nt][1] = *reinterpret_cast<uint32_t*>(sm + B_HI_OFF  + rb + k1);
            b_md[nt][0] = *reinterpret_cast<uint32_t*>(sm + B_MID_OFF + rb + k0);
            b_md[nt][1] = *reinterpret_cast<uint32_t*>(sm + B_MID_OFF + rb + k1);
        }
#pragma unroll
        for (int mt = 0; mt < 2; mt++)
#pragma unroll
            for (int nt = 0; nt < 2; nt++) {
                mma_bf16(d[mt][nt], a_hi[mt], b_hi[nt]);   // hi*hi
                mma_bf16(d[mt][nt], a_hi[mt], b_md[nt]);   // hi*mid
                mma_bf16(d[mt][nt], a_md[mt], b_hi[nt]);   // mid*hi
            }
    }

    // ================= Epilogue: D -> out =================
    float* outh = out + (size_t)h * SEQ_L;
#pragma unroll
    for (int mt = 0; mt < 2; mt++) {
        const int row = R0 + mt * 16 + g;             // c index
#pragma unroll
        for (int nt = 0; nt < 2; nt++) {
            const int col = nt * 8 + 2 * t;           // j index
            *reinterpret_cast<float2*>(outh + 16 * row + col) =
                make_float2(d[mt][nt][0], d[mt][nt][1]);
            *reinterpret_cast<float2*>(outh + 16 * (row + 8) + col) =
                make_float2(d[mt][nt][2], d[mt][nt][3]);
        }
    }
}

extern "C" void kernel_launch(void* const* d_in, const int* in_sizes, int n_in,
                              void* d_out, int out_size)
{
    const float* Cri   = (const float*)d_in[0];   // (1, H, N, 2)
    const float* logdt = (const float*)d_in[1];   // (H,)
    const float* Bri   = (const float*)d_in[2];   // (H, N, 2)  (n_ssm == H)
    const float* invAr = (const float*)d_in[3];   // (H, N)
    const float* Aim   = (const float*)d_in[4];   // (H, N)
    float* out = (float*)d_out;                   // (1, H, L)

    cudaFuncSetAttribute(ssk_hmma, cudaFuncAttributeMaxDynamicSharedMemorySize,
                         SMEM_BYTES);
    ssk_hmma<<<H_DIM, 128, SMEM_BYTES>>>(Cri, logdt, Bri, invAr, Aim, out);
}

// round 11
// speedup vs baseline: 1.5167x; 1.1167x over previous
#include <cuda_runtime.h>
#include <cuda_bf16.h>
#include <cstdint>

// Fixed shapes
#define H_DIM   1024
#define N_DIM   64
#define SEQ_L   2048
// Per-h GEMM: D[c=0..127, j=0..15] = sum_k A[c,k]*B[k,j],  l = 16c + j
//   A[c, 2n] = Re(Ct2 * r^(16c)),  A[c, 2n+1] = Im(...)
//   B[2n, j] = Re(r^j),            B[2n+1, j] = -Im(r^j)   (stored [j][kappa])
// bf16 split A = Ahi+Amid, B = Bhi+Bmid; D = AhBh + AhBm + AmBh.

// SMEM tiles: row-major, 256B rows, XOR-swizzle in 16B units by (row&7)<<4
#define A_HI_OFF   0        // 128 x 256B = 32768
#define A_MID_OFF  32768
#define B_HI_OFF   65536    // 16 x 256B = 4096
#define B_MID_OFF  69632
#define SMEM_BYTES 73728

__device__ __forceinline__ uint32_t smem_u32(const void* p) {
    uint32_t a;
    asm("{ .reg .u64 t; cvta.to.shared.u64 t, %1; cvt.u32.u64 %0, t; }" : "=r"(a) : "l"(p));
    return a;
}
__device__ __forceinline__ uint32_t cvt_bf16x2(float hi_f, float lo_f) {
    uint32_t r;
    asm("cvt.rn.bf16x2.f32 %0, %1, %2;" : "=r"(r) : "f"(hi_f), "f"(lo_f));
    return r;
}
// Split f32 pair into hi-bf16x2 + mid-bf16x2 (residual), store to both tiles.
__device__ __forceinline__ void split_store(char* sm, uint32_t addr,
                                            float lo, float hi, bool isA) {
    uint32_t pk = cvt_bf16x2(hi, lo);
    float lo_h = __uint_as_float(pk << 16);
    float hi_h = __uint_as_float(pk & 0xFFFF0000u);
    uint32_t pm = cvt_bf16x2(hi - hi_h, lo - lo_h);
    uint32_t oh = isA ? A_HI_OFF : B_HI_OFF;
    uint32_t om = isA ? A_MID_OFF : B_MID_OFF;
    *reinterpret_cast<uint32_t*>(sm + oh + addr) = pk;
    *reinterpret_cast<uint32_t*>(sm + om + addr) = pm;
}
__device__ __forceinline__ void ldsm4(uint32_t* r, uint32_t addr) {
    asm volatile("ldmatrix.sync.aligned.m8n8.x4.shared.b16 {%0,%1,%2,%3}, [%4];"
                 : "=r"(r[0]), "=r"(r[1]), "=r"(r[2]), "=r"(r[3]) : "r"(addr));
}
__device__ __forceinline__ void mma_bf16(float* d, const uint32_t* a,
                                         uint32_t b0, uint32_t b1) {
    asm volatile(
        "mma.sync.aligned.m16n8k16.row.col.f32.bf16.bf16.f32 "
        "{%0,%1,%2,%3}, {%4,%5,%6,%7}, {%8,%9}, {%0,%1,%2,%3};"
        : "+f"(d[0]), "+f"(d[1]), "+f"(d[2]), "+f"(d[3])
        : "r"(a[0]), "r"(a[1]), "r"(a[2]), "r"(a[3]), "r"(b0), "r"(b1));
}

__global__ void __launch_bounds__(256) ssk_hmma(
    const float* __restrict__ Cri, const float* __restrict__ logdt,
    const float* __restrict__ Bri, const float* __restrict__ invAr,
    const float* __restrict__ Aim, float* __restrict__ out)
{
    extern __shared__ __align__(1024) char sm[];
    const int tx = threadIdx.x;
    const int h  = blockIdx.x;

    // ================= Generation phase =================
    {
        const int n  = tx & 63;
        const int q4 = tx >> 6;                      // quarter 0..3
        const int idx = h * N_DIM + n;

        float cr = Cri[2 * idx], ci = Cri[2 * idx + 1];
        float br = Bri[2 * idx], bi = Bri[2 * idx + 1];
        float dt = __expf(logdt[h]);
        float Ar = -__expf(invAr[idx]);
        float Ai = Aim[idx];

        float zr = Ar * dt, zi = Ai * dt;
        float dr = 1.0f - 0.5f * zr, di = -0.5f * zi;
        float inv = 1.0f / (dr * dr + di * di);

        float bcr = br * cr - bi * ci;
        float bci = br * ci + bi * cr;
        float s = 2.0f * dt * inv;
        float ctr = (bcr * dr + bci * di) * s;       // Ct2 = 2*B*C*dt/den
        float cti = (bci * dr - bcr * di) * s;

        float nr = 1.0f + 0.5f * zr, ni = 0.5f * zi;
        float rr = (nr * dr + ni * di) * inv;        // r, |r| < 1
        float ri = (ni * dr - nr * di) * inv;

        // powers r^2, r^4, r^8, r^16 (= rho)
        float r2r = rr * rr - ri * ri,     r2i = 2.0f * rr * ri;
        float r4r = r2r * r2r - r2i * r2i, r4i = 2.0f * r2r * r2i;
        float r8r = r4r * r4r - r4i * r4i, r8i = 2.0f * r4r * r4i;
        float pr  = r8r * r8r - r8i * r8i, pi  = 2.0f * r8r * r8i;  // rho

        const uint32_t colb = (uint32_t)n * 4u;

        // ---- B rows j = 4*q4 .. +3 : (Re r^j, -Im r^j) ----
        {
            float vr = 1.0f, vi = 0.0f;
            if (q4 & 1) { vr = r4r; vi = r4i; }
            if (q4 & 2) {                            // *= r^8
                float t = vr * r8r - vi * r8i;
                vi = vr * r8i + vi * r8r;
                vr = t;
            }
#pragma unroll
            for (int i = 0; i < 4; i++) {
                int j = 4 * q4 + i;
                uint32_t addr = (uint32_t)j * 256u
                              + (colb ^ (((uint32_t)(j & 7)) << 4));
                split_store(sm, addr, vr, -vi, false);
                float t = vr * rr - vi * ri;         // v *= r
                vi = vr * ri + vi * rr;
                vr = t;
            }
        }

        // ---- A rows c = 32*q4 .. +31 : W = Ct2 * rho^c ----
        float wr = ctr, wi = cti;
        {
            float s32r = pr, s32i = pi;              // rho^32 via 5 squarings
#pragma unroll
            for (int i = 0; i < 5; i++) {
                float t = s32r * s32r - s32i * s32i;
                s32i = 2.0f * s32r * s32i;
                s32r = t;
            }
            float mr = 1.0f, mi = 0.0f;
            if (q4 & 1) { mr = s32r; mi = s32i; }
            if (q4 & 2) {
                float s64r = s32r * s32r - s32i * s32i;
                float s64i = 2.0f * s32r * s32i;
                float t = mr * s64r - mi * s64i;
                mi = mr * s64i + mi * s64r;
                mr = t;
            }
            float t = wr * mr - wi * mi;
            wi = wr * mi + wi * mr;
            wr = t;
        }
#pragma unroll 4
        for (int i = 0; i < 32; i++) {
            int c = 32 * q4 + i;
            uint32_t addr = (uint32_t)c * 256u
                          + (colb ^ (((uint32_t)(c & 7)) << 4));
            split_store(sm, addr, wr, wi, true);
            float t = wr * pr - wi * pi;             // w *= rho
            wi = wr * pi + wi * pr;
            wr = t;
        }
    }
    __syncthreads();

    // ================= MMA phase: 8 warps, one m16 tile each =================
    const int wid = tx >> 5;
    const int lid = tx & 31;
    const int R0  = wid * 16;

    float d[2][4];
#pragma unroll
    for (int nt = 0; nt < 2; nt++)
#pragma unroll
        for (int i = 0; i < 4; i++) d[nt][i] = 0.0f;

    // per-lane ldmatrix row/col-half (identical pattern for A and B x4)
    const uint32_t lrow = (uint32_t)(lid & 15);
    const uint32_t c16  = (uint32_t)(lid & 16);
    const uint32_t sbase = smem_u32(sm);
    const uint32_t a_rowb = sbase + (uint32_t)(R0 + (int)lrow) * 256u;
    const uint32_t a_swz  = (lrow & 7u) << 4;
    const uint32_t b_rowb = sbase + lrow * 256u;     // j rows 0..15
    const uint32_t b_swz  = a_swz;

#pragma unroll
    for (int kt = 0; kt < 8; kt++) {
        const uint32_t acol = ((uint32_t)(kt * 32) + c16) ^ a_swz;
        const uint32_t bcol = ((uint32_t)(kt * 32) + c16) ^ b_swz;

        uint32_t a_hi[4], a_md[4], bh[4], bm[4];
        ldsm4(a_hi, a_rowb + A_HI_OFF  + acol);
        ldsm4(a_md, a_rowb + A_MID_OFF + acol);
        ldsm4(bh,   b_rowb + B_HI_OFF  + bcol);      // m0/m1: nt0/nt1 b0, m2/m3: b1
        ldsm4(bm,   b_rowb + B_MID_OFF + bcol);

        mma_bf16(d[0], a_hi, bh[0], bh[2]);          // hi*hi nt0
        mma_bf16(d[1], a_hi, bh[1], bh[3]);          // hi*hi nt1
        mma_bf16(d[0], a_hi, bm[0], bm[2]);          // hi*mid
        mma_bf16(d[1], a_hi, bm[1], bm[3]);
        mma_bf16(d[0], a_md, bh[0], bh[2]);          // mid*hi
        mma_bf16(d[1], a_md, bh[1], bh[3]);
    }

    // ================= Epilogue =================
    float* outh = out + (size_t)h * SEQ_L;
    const int row = R0 + (lid >> 2);                 // c index
    const int col = 2 * (lid & 3);                   // j base
#pragma unroll
    for (int nt = 0; nt < 2; nt++) {
        *reinterpret_cast<float2*>(outh + 16 * row + nt * 8 + col) =
            make_float2(d[nt][0], d[nt][1]);
        *reinterpret_cast<float2*>(outh + 16 * (row + 8) + nt * 8 + col) =
            make_float2(d[nt][2], d[nt][3]);
    }
}

extern "C" void kernel_launch(void* const* d_in, const int* in_sizes, int n_in,
                              void* d_out, int out_size)
{
    const float* Cri   = (const float*)d_in[0];   // (1, H, N, 2)
    const float* logdt = (const float*)d_in[1];   // (H,)
    const float* Bri   = (const float*)d_in[2];   // (H, N, 2)  (n_ssm == H)
    const float* invAr = (const float*)d_in[3];   // (H, N)
    const float* Aim   = (const float*)d_in[4];   // (H, N)
    float* out = (float*)d_out;                   // (1, H, L)

    cudaFuncSetAttribute(ssk_hmma, cudaFuncAttributeMaxDynamicSharedMemorySize,
                         SMEM_BYTES);
    ssk_hmma<<<H_DIM, 256, SMEM_BYTES>>>(Cri, logdt, Bri, invAr, Aim, out);
}

// round 12
// speedup vs baseline: 1.8246x; 1.2030x over previous
#include <cuda_runtime.h>
#include <cuda_bf16.h>
#include <cstdint>

// Fixed shapes
#define H_DIM   1024
#define N_DIM   64
#define SEQ_L   2048
// Per-h GEMM (J=32 split):  l = 32c + j,  c = 0..63, j = 0..31
//   D[c, j] = sum_kappa A[c, kappa] * B[kappa, j]
//   A[c, 2n] = Re(Ct2 * r^(32c)),  A[c, 2n+1] = Im(...)     (64 x 128)
//   B[2n, j] = Re(r^j),            B[2n+1, j] = -Im(r^j)    (stored [j][kappa], 32 x 128)
// bf16 split X = Xhi + Xmid; D = AhBh + AhBm + AmBh.

// SMEM tiles: row-major, 256B rows, XOR-swizzle in 16B units by (row&7)<<4
#define A_HI_OFF   0        // 64 x 256B = 16384
#define A_MID_OFF  16384
#define B_HI_OFF   32768    // 32 x 256B = 8192
#define B_MID_OFF  40960
#define SMEM_BYTES 49152    // 48KB -> 4 CTAs/SM

__device__ __forceinline__ uint32_t smem_u32(const void* p) {
    uint32_t a;
    asm("{ .reg .u64 t; cvta.to.shared.u64 t, %1; cvt.u32.u64 %0, t; }" : "=r"(a) : "l"(p));
    return a;
}
__device__ __forceinline__ uint32_t cvt_bf16x2(float hi_f, float lo_f) {
    uint32_t r;
    asm("cvt.rn.bf16x2.f32 %0, %1, %2;" : "=r"(r) : "f"(hi_f), "f"(lo_f));
    return r;
}
// Split f32 pair into hi-bf16x2 + mid-bf16x2 (residual), store to both tiles.
__device__ __forceinline__ void split_store(char* sm, uint32_t addr,
                                            float lo, float hi, bool isA) {
    uint32_t pk = cvt_bf16x2(hi, lo);
    float lo_h = __uint_as_float(pk << 16);
    float hi_h = __uint_as_float(pk & 0xFFFF0000u);
    uint32_t pm = cvt_bf16x2(hi - hi_h, lo - lo_h);
    uint32_t oh = isA ? A_HI_OFF : B_HI_OFF;
    uint32_t om = isA ? A_MID_OFF : B_MID_OFF;
    *reinterpret_cast<uint32_t*>(sm + oh + addr) = pk;
    *reinterpret_cast<uint32_t*>(sm + om + addr) = pm;
}
__device__ __forceinline__ void ldsm4(uint32_t* r, uint32_t addr) {
    asm volatile("ldmatrix.sync.aligned.m8n8.x4.shared.b16 {%0,%1,%2,%3}, [%4];"
                 : "=r"(r[0]), "=r"(r[1]), "=r"(r[2]), "=r"(r[3]) : "r"(addr));
}
__device__ __forceinline__ void mma_bf16(float* d, const uint32_t* a,
                                         uint32_t b0, uint32_t b1) {
    asm volatile(
        "mma.sync.aligned.m16n8k16.row.col.f32.bf16.bf16.f32 "
        "{%0,%1,%2,%3}, {%4,%5,%6,%7}, {%8,%9}, {%0,%1,%2,%3};"
        : "+f"(d[0]), "+f"(d[1]), "+f"(d[2]), "+f"(d[3])
        : "r"(a[0]), "r"(a[1]), "r"(a[2]), "r"(a[3]), "r"(b0), "r"(b1));
}

__global__ void __launch_bounds__(256) ssk_hmma(
    const float* __restrict__ Cri, const float* __restrict__ logdt,
    const float* __restrict__ Bri, const float* __restrict__ invAr,
    const float* __restrict__ Aim, float* __restrict__ out)
{
    extern __shared__ __align__(1024) char sm[];
    const int tx = threadIdx.x;
    const int h  = blockIdx.x;

    // ================= Generation phase =================
    {
        const int n  = tx & 63;
        const int q4 = tx >> 6;                      // quarter 0..3
        const int idx = h * N_DIM + n;

        float cr = Cri[2 * idx], ci = Cri[2 * idx + 1];
        float br = Bri[2 * idx], bi = Bri[2 * idx + 1];
        float dt = __expf(logdt[h]);
        float Ar = -__expf(invAr[idx]);
        float Ai = Aim[idx];

        float zr = Ar * dt, zi = Ai * dt;
        float dr = 1.0f - 0.5f * zr, di = -0.5f * zi;
        float inv = 1.0f / (dr * dr + di * di);

        float bcr = br * cr - bi * ci;
        float bci = br * ci + bi * cr;
        float s = 2.0f * dt * inv;
        float ctr = (bcr * dr + bci * di) * s;       // Ct2 = 2*B*C*dt/den
        float cti = (bci * dr - bcr * di) * s;

        float nr = 1.0f + 0.5f * zr, ni = 0.5f * zi;
        float rr = (nr * dr + ni * di) * inv;        // r, |r| < 1
        float ri = (ni * dr - nr * di) * inv;

        // powers r^2, r^4, r^8, r^16, r^32 (= rho)
        float r2r  = rr * rr - ri * ri,      r2i  = 2.0f * rr * ri;
        float r4r  = r2r * r2r - r2i * r2i,  r4i  = 2.0f * r2r * r2i;
        float r8r  = r4r * r4r - r4i * r4i,  r8i  = 2.0f * r4r * r4i;
        float r16r = r8r * r8r - r8i * r8i,  r16i = 2.0f * r8r * r8i;
        float pr   = r16r * r16r - r16i * r16i, pi = 2.0f * r16r * r16i;  // rho

        const uint32_t colb = (uint32_t)n * 4u;

        // ---- B rows j = 8*q4 .. +7 : (Re r^j, -Im r^j) ----
        {
            float vr = 1.0f, vi = 0.0f;
            if (q4 & 1) { vr = r8r; vi = r8i; }
            if (q4 & 2) {                            // *= r^16
                float t = vr * r16r - vi * r16i;
                vi = vr * r16i + vi * r16r;
                vr = t;
            }
            const uint32_t jb = (uint32_t)(8 * q4) * 256u;
#pragma unroll
            for (int i = 0; i < 8; i++) {
                uint32_t addr = jb + (uint32_t)i * 256u
                              + (colb ^ (((uint32_t)i) << 4));
                split_store(sm, addr, vr, -vi, false);
                float t = vr * rr - vi * ri;         // v *= r
                vi = vr * ri + vi * rr;
                vr = t;
            }
        }

        // ---- A rows c = 16*q4 .. +15 : W = Ct2 * rho^c ----
        float wr = ctr, wi = cti;
        {
            // rho^16 via 4 squarings of rho
            float s16r = pr, s16i = pi;
#pragma unroll
            for (int i = 0; i < 4; i++) {
                float t = s16r * s16r - s16i * s16i;
                s16i = 2.0f * s16r * s16i;
                s16r = t;
            }
            float mr = 1.0f, mi = 0.0f;
            if (q4 & 1) { mr = s16r; mi = s16i; }
            if (q4 & 2) {
                float s32r = s16r * s16r - s16i * s16i;
                float s32i = 2.0f * s16r * s16i;
                float t = mr * s32r - mi * s32i;
                mi = mr * s32i + mi * s32r;
                mr = t;
            }
            float t = wr * mr - wi * mi;
            wi = wr * mi + wi * mr;
            wr = t;
        }
        const uint32_t cb = (uint32_t)(16 * q4) * 256u;
#pragma unroll
        for (int i = 0; i < 16; i++) {
            uint32_t addr = cb + (uint32_t)i * 256u
                          + (colb ^ (((uint32_t)(i & 7)) << 4));
            split_store(sm, addr, wr, wi, true);
            float t = wr * pr - wi * pi;             // w *= rho
            wi = wr * pi + wi * pr;
            wr = t;
        }
    }
    __syncthreads();

    // ====== MMA phase: 8 warps = (mt 0..3) x (nh 0..1), m16 x n16 each ======
    const int wid = tx >> 5;
    const int lid = tx & 31;
    const int mt  = wid & 3;
    const int nh  = wid >> 2;

    float d[2][4];
#pragma unroll
    for (int nt = 0; nt < 2; nt++)
#pragma unroll
        for (int i = 0; i < 4; i++) d[nt][i] = 0.0f;

    const uint32_t lrow = (uint32_t)(lid & 15);
    const uint32_t c16  = (uint32_t)(lid & 16);      // k-half select (16B)
    const uint32_t swz  = (lrow & 7u) << 4;
    const uint32_t sbase = smem_u32(sm);
    const uint32_t a_rowb = sbase + ((uint32_t)(mt * 16) + lrow) * 256u;
    const uint32_t b_rowb = sbase + ((uint32_t)(nh * 16) + lrow) * 256u;

#pragma unroll
    for (int kt = 0; kt < 8; kt++) {
        const uint32_t col = ((uint32_t)(kt * 32) + c16) ^ swz;

        uint32_t a_hi[4], a_md[4], bh[4], bm[4];
        ldsm4(a_hi, a_rowb + A_HI_OFF  + col);
        ldsm4(a_md, a_rowb + A_MID_OFF + col);
        ldsm4(bh,   b_rowb + B_HI_OFF  + col);  // m0/m1: nt0/nt1 (k lo), m2/m3: (k hi)
        ldsm4(bm,   b_rowb + B_MID_OFF + col);

        mma_bf16(d[0], a_hi, bh[0], bh[2]);     // hi*hi  nt0
        mma_bf16(d[1], a_hi, bh[1], bh[3]);     // hi*hi  nt1
        mma_bf16(d[0], a_hi, bm[0], bm[2]);     // hi*mid
        mma_bf16(d[1], a_hi, bm[1], bm[3]);
        mma_bf16(d[0], a_md, bh[0], bh[2]);     // mid*hi
        mma_bf16(d[1], a_md, bh[1], bh[3]);
    }

    // ================= Epilogue: D[c, j] -> out[h, 32c + j] =================
    float* outh = out + (size_t)h * SEQ_L;
    const int row = mt * 16 + (lid >> 2);            // c index (and row+8)
    const int jb  = nh * 16 + 2 * (lid & 3);         // j base
#pragma unroll
    for (int nt = 0; nt < 2; nt++) {
        *reinterpret_cast<float2*>(outh + 32 * row + jb + 8 * nt) =
            make_float2(d[nt][0], d[nt][1]);
        *reinterpret_cast<float2*>(outh + 32 * (row + 8) + jb + 8 * nt) =
            make_float2(d[nt][2], d[nt][3]);
    }
}

extern "C" void kernel_launch(void* const* d_in, const int* in_sizes, int n_in,
                              void* d_out, int out_size)
{
    const float* Cri   = (const float*)d_in[0];   // (1, H, N, 2)
    const float* logdt = (const float*)d_in[1];   // (H,)
    const float* Bri   = (const float*)d_in[2];   // (H, N, 2)  (n_ssm == H)
    const float* invAr = (const float*)d_in[3];   // (H, N)
    const float* Aim   = (const float*)d_in[4];   // (H, N)
    float* out = (float*)d_out;                   // (1, H, L)

    cudaFuncSetAttribute(ssk_hmma, cudaFuncAttributeMaxDynamicSharedMemorySize,
                         SMEM_BYTES);
    ssk_hmma<<<H_DIM, 256, SMEM_BYTES>>>(Cri, logdt, Bri, invAr, Aim, out);
}